// round 6
// baseline (speedup 1.0000x reference)
#include <cuda_runtime.h>
#include <cuda_bf16.h>

#define NGRID   10000
#define NSTEPS  730
#define LENF    15
#define NEARZEROF 1e-5f
#define UNR     5          // group size; 730 % 10 == 0 (ping-pong pairs)

// 29.2 MB scratch for raw discharge q (device global: no runtime alloc)
__device__ float g_Q[(size_t)NSTEPS * NGRID];

// ---------------------------------------------------------------------------
// Kernel 1: sequential HBV scan, one thread per grid cell, writes raw q.
// ---------------------------------------------------------------------------
__global__ __launch_bounds__(64, 1)
void hbv_scan_kernel(const float* __restrict__ x_phy,   // [NSTEPS, NGRID, 3]
                     const float* __restrict__ phy)     // [NGRID, 16]
{
    int g = blockIdx.x * blockDim.x + threadIdx.x;
    if (g >= NGRID) return;

    const float* ps = phy + g * 16;
    float BETA   = ps[0]  * 5.0f   + 1.0f;
    float FC     = ps[1]  * 950.0f + 50.0f;
    float K0     = ps[2]  * 0.85f  + 0.05f;
    float K1     = ps[3]  * 0.49f  + 0.01f;
    float K2     = ps[4]  * 0.199f + 0.001f;
    float LP     = ps[5]  * 0.8f   + 0.2f;
    float PERC   = ps[6]  * 10.0f;
    float UZL    = ps[7]  * 100.0f;
    float TT     = ps[8]  * 5.0f   - 2.5f;
    float CFMAX  = ps[9]  * 9.5f   + 0.5f;
    float CFR    = ps[10] * 0.1f;
    float CWH    = ps[11] * 0.2f;
    float BETAET = ps[12] * 4.7f   + 0.3f;
    float C      = ps[13];

    float invFC    = 1.0f / FC;
    float invLPFC  = 1.0f / (LP * FC);
    float CFRCFMAX = CFR * CFMAX;

    float snow = NEARZEROF, melt = NEARZEROF, sm = NEARZEROF,
          suz = NEARZEROF, slz = NEARZEROF;
    float cslz = C * slz;          // off-chain capillary precompute
    float kcap = cslz * invFC;

    const int rowstride = NGRID * 3;
    const float* xbase = x_phy + (size_t)g * 3;
    float* qrow = g_Q + g;

    float Ap[UNR], Atm[UNR], Ape[UNR];
    float Bp[UNR], Btm[UNR], Bpe[UNR];

#define LOADG(P, T, E, GRP)                                             \
    _Pragma("unroll")                                                   \
    for (int u = 0; u < UNR; u++) {                                     \
        int idx = (GRP) * UNR + u;                                      \
        if (idx >= NSTEPS) idx = NSTEPS - 1;                            \
        const float* xn = xbase + (size_t)idx * rowstride;              \
        P[u] = __ldg(xn + 0); T[u] = __ldg(xn + 1); E[u] = __ldg(xn + 2); \
    }

#define STEPS(P, T, E, BASE)                                            \
    _Pragma("unroll")                                                   \
    for (int u = 0; u < UNR; u++) {                                     \
        float p  = P[u];                                                \
        float tm = T[u];                                                \
        float pe = E[u];                                                \
        /* input-only precomputes (off the carried chain) */            \
        float rain     = (tm >= TT) ? p : 0.0f;                         \
        float snowfall = p - rain;                                      \
        float mpot     = fmaxf(CFMAX    * (tm - TT), 0.0f);             \
        float rpot     = fmaxf(CFRCFMAX * (TT - tm), 0.0f);             \
        /* soil_wet from previous sm: MUFU overlaps snow chain */       \
        float soil_wet = fminf(__powf(sm * invFC, BETA), 1.0f);         \
        /* snow bucket, re-derived to max() form */                     \
        float sp     = snow + snowfall;                                 \
        float snow1  = fmaxf(sp - mpot, 0.0f);                          \
        float m      = sp - snow1;                                      \
        float melt1  = melt + m;                                        \
        float melt2  = fmaxf(melt1 - rpot, 0.0f);                       \
        float refr   = melt1 - melt2;                                   \
        snow         = snow1 + refr;                                    \
        float tosoil = fmaxf(melt2 - CWH * snow, 0.0f);                 \
        melt         = melt2 - tosoil;                                  \
        /* soil bucket (chain-shortened, exact) */                      \
        float rt       = rain + tosoil;                                 \
        float recharge = rt * soil_wet;                                 \
        float sm_pre   = fmaf(rt, 1.0f - soil_wet, sm);                 \
        float sm_c     = fminf(sm_pre, FC);                             \
        float excess   = sm_pre - sm_c;                                 \
        float evapfac  = fminf(__powf(sm_pre * invLPFC, BETAET), 1.0f); \
        float sm_et    = fmaxf(fmaf(-pe, evapfac, sm_c), NEARZEROF);    \
        float cap      = fminf(slz, fmaf(-kcap, sm_et, cslz));          \
        sm             = fmaxf(sm_et + cap, NEARZEROF);                 \
        slz            = fmaxf(slz - cap, NEARZEROF);                   \
        /* response routine */                                          \
        suz += recharge + excess;                                       \
        float percact = fminf(suz, PERC);                               \
        suz -= percact;                                                 \
        float q0 = K0 * fmaxf(suz - UZL, 0.0f);                         \
        suz -= q0;                                                      \
        float q1 = K1 * suz;                                            \
        suz -= q1;                                                      \
        slz += percact;                                                 \
        float q2 = K2 * slz;                                            \
        slz -= q2;                                                      \
        cslz = C * slz;                                                 \
        kcap = cslz * invFC;                                            \
        qrow[(size_t)((BASE) + u) * NGRID] = q0 + q1 + q2;              \
    }

    // prologue: groups 0 and 1
    LOADG(Ap, Atm, Ape, 0)
    LOADG(Bp, Btm, Bpe, 1)

    for (int base = 0; base < NSTEPS; base += 2 * UNR) {
        int grp = base / UNR;
        STEPS(Ap, Atm, Ape, base)
        LOADG(Ap, Atm, Ape, grp + 2)
        STEPS(Bp, Btm, Bpe, base + UNR)
        LOADG(Bp, Btm, Bpe, grp + 3)
    }
#undef LOADG
#undef STEPS
}

// ---------------------------------------------------------------------------
// Kernel 2: gamma-kernel routing convolution, parallel over (t, g).
// Tile of 75 time steps (multiple of 15 -> static circular-buffer indices).
// ---------------------------------------------------------------------------
#define TTILE 75

__global__ __launch_bounds__(128, 1)
void hbv_rout_kernel(const float* __restrict__ phy,   // [NGRID, 16]
                     float* __restrict__ out)         // [NSTEPS, NGRID]
{
    int g = blockIdx.x * blockDim.x + threadIdx.x;
    if (g >= NGRID) return;

    // ln(k + 0.5), k = 0..14
    const float LOGTG[LENF] = {
        -0.69314718f, 0.40546511f, 0.91629073f, 1.25276297f, 1.50407740f,
         1.70474809f, 1.87180218f, 2.01490302f, 2.14006616f, 2.25129180f,
         2.35137526f, 2.44234704f, 2.52572864f, 2.60268969f, 2.67418505f };

    float aa    = fmaxf(phy[g * 16 + 14] * 2.9f, 0.0f) + 0.1f;
    float theta = fmaxf(phy[g * 16 + 15] * 6.5f, 0.0f) + 0.5f;
    float invTheta = 1.0f / theta;
    float am1 = aa - 1.0f;

    // normalized gamma weights (gammaln & a*log(theta) cancel)
    float w[LENF];
    float wsum = 0.0f;
#pragma unroll
    for (int k = 0; k < LENF; k++) {
        float tg = (float)k + 0.5f;
        float e = expf(fmaf(am1, LOGTG[k], -tg * invTheta));
        w[k] = e;
        wsum += e;
    }
    float invw = 1.0f / wsum;
#pragma unroll
    for (int k = 0; k < LENF; k++) w[k] *= invw;

    int t0 = blockIdx.y * TTILE;          // multiple of 15
    const float* qcol = g_Q + g;
    float* ocol = out + g;

    // circular history: h[tau % 15] holds Q[tau]
    float h[LENF];
#pragma unroll
    for (int j = 0; j < LENF - 1; j++) {
        int t = t0 - (LENF - 1) + j;      // t0-14 .. t0-1 -> slots 1..14
        h[j + 1] = (t >= 0) ? qcol[(size_t)t * NGRID] : 0.0f;
    }
    h[0] = 0.0f;

#pragma unroll
    for (int tt = 0; tt < TTILE; tt++) {
        int t = t0 + tt;
        if (t < NSTEPS) {
            h[tt % LENF] = qcol[(size_t)t * NGRID];
            float qr = 0.0f;
#pragma unroll
            for (int k = 0; k < LENF; k++) {
                int idx = (tt - k + LENF) % LENF;   // compile-time after unroll
                qr = fmaf(w[k], h[idx], qr);
            }
            ocol[(size_t)t * NGRID] = qr;
        }
    }
}

extern "C" void kernel_launch(void* const* d_in, const int* in_sizes, int n_in,
                              void* d_out, int out_size) {
    const float* x_phy = (const float*)d_in[0];
    const float* phy   = (const float*)d_in[1];
    float* out         = (float*)d_out;
    (void)in_sizes; (void)n_in; (void)out_size;

    // scan: 64-thread blocks -> 157 blocks, spread over all 148 SMs
    hbv_scan_kernel<<<(NGRID + 63) / 64, 64>>>(x_phy, phy);

    // routing: grid (g-tiles, t-tiles)
    dim3 rgrid((NGRID + 127) / 128, (NSTEPS + TTILE - 1) / TTILE);
    hbv_rout_kernel<<<rgrid, 128>>>(phy, out);
}